// round 5
// baseline (speedup 1.0000x reference)
#include <cuda_runtime.h>
#include <math.h>

// QualiaCNN, two-phase:
//  Phase 1: high-occupancy entropy partial reduction (8 blocks/sample),
//           the ONLY pass over the 13.6 MB input -> bandwidth-bound.
//  Phase 2: per-sample finalize. Expected path (i.i.d. normal input,
//           ent ~ 9.2 >> 2.0): write two zeros, exit. Slow path computes
//           the full CNN block-locally (correct for arbitrary inputs).

#define HH 13
#define WW 1024
#define BB 256
#define H1 6
#define W1 512
#define H2 3
#define W2 256
#define FLAT (32 * H2 * W2)   // 24576
#define NPIX (HH * WW)        // 13312
#define NV4  (NPIX / 4)       // 3328
#define CH   8                // phase-1 chunks per sample
#define CV4  (NV4 / CH)       // 416 float4 per chunk
#define P1T  256              // phase-1 block size
#define P2T  1024             // phase-2 block size

__device__ float g_partS[BB * CH];
__device__ float g_partT[BB * CH];
// Scratch for the (rare) active-sample path.
__device__ float g_h1[BB * 16 * H1 * W1];
__device__ float g_h2[BB * 32 * H2 * W2];

// Fast ln(v) for v > 0: bit-trick log2 scaled by ln2.
// |err| < ~0.06 nats; entropy margin to the 2.0 threshold is ~7 nats.
__device__ __forceinline__ float fast_ln(float v) {
    return (float)__float_as_int(v) * 8.2629582e-8f - 87.989971f;
}

// ---------------------------------------------------------------------------
// Phase 1: partial S = sum(v), T = sum(v*ln v), v = |x| + 1e-10
// grid = BB*CH blocks of P1T threads; block blk covers chunk (blk%CH) of
// sample (blk/CH).
// ---------------------------------------------------------------------------
__global__ __launch_bounds__(P1T) void entropy_partial(const float* __restrict__ x)
{
    const int blk = blockIdx.x;
    const int b = blk >> 3;          // CH == 8
    const int c = blk & 7;
    const int tid = threadIdx.x;

    const float4* xv = (const float4*)(x + (size_t)b * NPIX) + c * CV4;

    float S = 0.f, T = 0.f;
#pragma unroll 2
    for (int i = tid; i < CV4; i += P1T) {
        float4 q = xv[i];
        float v0 = fabsf(q.x) + 1e-10f;
        float v1 = fabsf(q.y) + 1e-10f;
        float v2 = fabsf(q.z) + 1e-10f;
        float v3 = fabsf(q.w) + 1e-10f;
        S += v0 + v1 + v2 + v3;
        T += v0 * fast_ln(v0) + v1 * fast_ln(v1)
           + v2 * fast_ln(v2) + v3 * fast_ln(v3);
    }
#pragma unroll
    for (int o = 16; o; o >>= 1) {
        S += __shfl_down_sync(0xFFFFFFFFu, S, o);
        T += __shfl_down_sync(0xFFFFFFFFu, T, o);
    }
    __shared__ float sS[8], sT[8];
    const int lane = tid & 31, warp = tid >> 5;
    if (lane == 0) { sS[warp] = S; sT[warp] = T; }
    __syncthreads();
    if (warp == 0 && lane < (P1T >> 5)) {
        S = sS[lane];
        T = sT[lane];
#pragma unroll
        for (int o = 4; o; o >>= 1) {
            S += __shfl_down_sync(0xFFu, S, o);
            T += __shfl_down_sync(0xFFu, T, o);
        }
        if (lane == 0) { g_partS[blk] = S; g_partT[blk] = T; }
    }
}

// ---------------------------------------------------------------------------
// Phase 2: finalize mask; fast path writes zeros; slow path = full CNN.
// grid = BB blocks of P2T threads.
// ---------------------------------------------------------------------------
__global__ __launch_bounds__(P2T) void qualia_finalize(
    const float* __restrict__ x,
    const float* __restrict__ w1, const float* __restrict__ b1,
    const float* __restrict__ w2, const float* __restrict__ b2,
    const float* __restrict__ fw1, const float* __restrict__ fb1,
    const float* __restrict__ fw2, const float* __restrict__ fb2,
    float* __restrict__ out)
{
    const int b = blockIdx.x;
    const int tid = threadIdx.x;
    const int lane = tid & 31;
    const int warp = tid >> 5;

    __shared__ int s_active;
    if (tid < 32) {
        float S = (lane < CH) ? g_partS[b * CH + lane] : 0.f;
        float T = (lane < CH) ? g_partT[b * CH + lane] : 0.f;
#pragma unroll
        for (int o = 4; o; o >>= 1) {
            S += __shfl_down_sync(0xFFFFFFFFu, S, o);
            T += __shfl_down_sync(0xFFFFFFFFu, T, o);
        }
        if (lane == 0) {
            float ent = logf(S) - T / S;
            s_active = (ent < 2.0f) ? 1 : 0;
        }
    }
    __syncthreads();

    if (!s_active) {                       // expected path: mask == 0
        if (tid < 2) out[b * 2 + tid] = 0.f;
        return;
    }

    // ===== Slow path (active sample): full CNN, block-local. =====
    const float* xb = x + (size_t)b * NPIX;

    // conv1 (1->16, 3x3 SAME) + relu + maxpool2 -> g_h1
    float* h1 = g_h1 + (size_t)b * 16 * H1 * W1;
    for (int idx = tid; idx < 16 * H1 * W1; idx += P2T) {
        int oc = idx / (H1 * W1);
        int p  = idx % (H1 * W1);
        int ph = p / W1, pw = p % W1;
        float wk[9];
#pragma unroll
        for (int i = 0; i < 9; i++) wk[i] = w1[oc * 9 + i];
        float bias = b1[oc];
        float m = 0.f;
#pragma unroll
        for (int dy = 0; dy < 2; dy++) {
#pragma unroll
            for (int dx = 0; dx < 2; dx++) {
                int r = 2 * ph + dy, c = 2 * pw + dx;
                float acc = bias;
#pragma unroll
                for (int kr = 0; kr < 3; kr++) {
                    int rr = r + kr - 1;
                    if ((unsigned)rr >= (unsigned)HH) continue;
#pragma unroll
                    for (int kc = 0; kc < 3; kc++) {
                        int cc = c + kc - 1;
                        if ((unsigned)cc >= (unsigned)WW) continue;
                        acc += xb[rr * WW + cc] * wk[kr * 3 + kc];
                    }
                }
                m = fmaxf(m, fmaxf(acc, 0.f));
            }
        }
        h1[idx] = m;
    }
    __syncthreads();

    // conv2 (16->32, 3x3 SAME) + relu + maxpool2 -> g_h2
    float* h2 = g_h2 + (size_t)b * FLAT;
    for (int idx = tid; idx < 32 * H2 * W2; idx += P2T) {
        int oc = idx / (H2 * W2);
        int p  = idx % (H2 * W2);
        int ph = p / W2, pw = p % W2;
        float bias = b2[oc];
        float m = 0.f;
#pragma unroll
        for (int dy = 0; dy < 2; dy++) {
#pragma unroll
            for (int dx = 0; dx < 2; dx++) {
                int r = 2 * ph + dy, c = 2 * pw + dx;
                float acc = bias;
                for (int ic = 0; ic < 16; ic++) {
                    const float* inp = h1 + ic * (H1 * W1);
                    const float* wkp = w2 + (oc * 16 + ic) * 9;
#pragma unroll
                    for (int kr = 0; kr < 3; kr++) {
                        int rr = r + kr - 1;
                        if ((unsigned)rr >= (unsigned)H1) continue;
#pragma unroll
                        for (int kc = 0; kc < 3; kc++) {
                            int cc = c + kc - 1;
                            if ((unsigned)cc >= (unsigned)W1) continue;
                            acc += inp[rr * W1 + cc] * wkp[kr * 3 + kc];
                        }
                    }
                }
                m = fmaxf(m, fmaxf(acc, 0.f));
            }
        }
        h2[idx] = m;
    }
    __syncthreads();

    // fc1: 24576 -> 128 + relu
    __shared__ float s_fc1[128];
    for (int j = warp; j < 128; j += 32) {
        const float* wr = fw1 + (size_t)j * FLAT;
        float acc = 0.f;
        for (int k = lane; k < FLAT; k += 32) acc += h2[k] * wr[k];
#pragma unroll
        for (int o = 16; o; o >>= 1) acc += __shfl_down_sync(0xFFFFFFFFu, acc, o);
        if (lane == 0) s_fc1[j] = fmaxf(acc + fb1[j], 0.f);
    }
    __syncthreads();

    // fc2: 128 -> 2 (mask == 1)
    if (warp < 2) {
        const float* wr = fw2 + warp * 128;
        float acc = 0.f;
#pragma unroll
        for (int k = lane; k < 128; k += 32) acc += s_fc1[k] * wr[k];
#pragma unroll
        for (int o = 16; o; o >>= 1) acc += __shfl_down_sync(0xFFFFFFFFu, acc, o);
        if (lane == 0) out[b * 2 + warp] = acc + fb2[warp];
    }
}

extern "C" void kernel_launch(void* const* d_in, const int* in_sizes, int n_in,
                              void* d_out, int out_size) {
    const float* x   = (const float*)d_in[0];
    const float* w1  = (const float*)d_in[1];
    const float* b1  = (const float*)d_in[2];
    const float* w2  = (const float*)d_in[3];
    const float* b2  = (const float*)d_in[4];
    const float* fw1 = (const float*)d_in[5];
    const float* fb1 = (const float*)d_in[6];
    const float* fw2 = (const float*)d_in[7];
    const float* fb2 = (const float*)d_in[8];
    float* out = (float*)d_out;

    entropy_partial<<<BB * CH, P1T>>>(x);
    qualia_finalize<<<BB, P2T>>>(x, w1, b1, w2, b2, fw1, fb1, fw2, fb2, out);
}